// round 4
// baseline (speedup 1.0000x reference)
#include <cuda_runtime.h>

#define D_IN     3072
#define H1       32
#define OUT_N    10
#define R_TILE   128           // rows per block
#define KC       64            // K chunk
#define KP       68            // padded smem row stride (floats)
#define NTHREADS 128
#define N_ROWS   32768

__device__ float g_Scol[H1];   // column sums of w1 (per output j)

// ---------------------------------------------------------------------------
// Kernel 1: S_j = sum_k w1[j,k]   (32 warps, one per j)
// ---------------------------------------------------------------------------
__global__ void colsum_kernel(const float* __restrict__ w1) {
    int j    = threadIdx.x >> 5;
    int lane = threadIdx.x & 31;
    const float* row = w1 + j * D_IN;
    float s = 0.f;
    for (int k = lane; k < D_IN; k += 32) s += row[k];
    #pragma unroll
    for (int m = 16; m; m >>= 1) s += __shfl_xor_sync(0xffffffffu, s, m);
    if (lane == 0) g_Scol[j] = s;
}

// ---------------------------------------------------------------------------
// Kernel 2: fused  stats + (x @ w1^T) + norm-correction + L1/L2/L3 + LeakyReLU
// ---------------------------------------------------------------------------
__global__ __launch_bounds__(NTHREADS) void fused_kernel(
    const float* __restrict__ x,  const float* __restrict__ w1,
    const float* __restrict__ b1, const float* __restrict__ w2,
    const float* __restrict__ b2, const float* __restrict__ w3,
    const float* __restrict__ b3, float* __restrict__ out)
{
    extern __shared__ float sm[];
    float* xs   = sm;                          // R_TILE*KP = 8704 floats
    float* ws   = xs + R_TILE * KP;            // H1*KP     = 2176
    float* sumS = ws + H1 * KP;                // 128
    float* sqS  = sumS + R_TILE;               // 128
    float* w2S  = sqS + R_TILE;                // 32*33 = 1056
    float* w3S  = w2S + H1 * 33;               // 32*33 = 1056 (zero padded)
    float* b1S  = w3S + H1 * 33;               // 32
    float* b2S  = b1S + H1;                    // 32
    float* b3S  = b2S + H1;                    // 32 (zero padded)
    float* ScS  = b3S + H1;                    // 32

    const int tid     = threadIdx.x;
    const int rowbase = blockIdx.x * R_TILE;

    // ---- init small smem ----
    for (int i = tid; i < H1 * 33; i += NTHREADS) { w3S[i] = 0.f; }
    for (int i = tid; i < H1 * H1; i += NTHREADS) {
        w2S[(i >> 5) * 33 + (i & 31)] = w2[i];
    }
    for (int i = tid; i < OUT_N * H1; i += NTHREADS) {
        // filled after the zero pass — need a sync; do it below instead
    }
    if (tid < R_TILE) { sumS[tid] = 0.f; sqS[tid] = 0.f; }
    if (tid < H1) {
        b1S[tid] = b1[tid];
        b2S[tid] = b2[tid];
        b3S[tid] = (tid < OUT_N) ? b3[tid] : 0.f;
        ScS[tid] = g_Scol[tid];
    }
    __syncthreads();   // w3S zeros visible before filling real rows
    for (int i = tid; i < OUT_N * H1; i += NTHREADS) {
        w3S[(i >> 5) * 33 + (i & 31)] = w3[i];
    }
    __syncthreads();

    // ---- GEMM register tile: 8 rows x 4 cols ----
    const int rg = tid >> 3;     // 0..15 row group
    const int cg = tid & 7;      // 0..7  col group
    float acc[8][4];
    #pragma unroll
    for (int i = 0; i < 8; i++)
        #pragma unroll
        for (int j = 0; j < 4; j++) acc[i][j] = 0.f;

    const int wrp  = tid >> 5;
    const int lane = tid & 31;
    const int sub  = lane & 7;
    const int rloc = lane >> 3;

    for (int kb = 0; kb < D_IN / KC; kb++) {
        const int k0 = kb * KC;
        // load x tile (128 rows x 64 k), coalesced float4
        #pragma unroll
        for (int i = 0; i < 16; i++) {
            int idx = tid + NTHREADS * i;        // 0..2047
            int r   = idx >> 4;
            int k4  = idx & 15;
            float4 v = *(const float4*)(x + (size_t)(rowbase + r) * D_IN + k0 + k4 * 4);
            *(float4*)(xs + r * KP + k4 * 4) = v;
        }
        // load w tile (32 x 64)
        #pragma unroll
        for (int i = 0; i < 4; i++) {
            int idx = tid + NTHREADS * i;        // 0..511
            int c   = idx >> 4;
            int k4  = idx & 15;
            float4 v = *(const float4*)(w1 + (size_t)c * D_IN + k0 + k4 * 4);
            *(float4*)(ws + c * KP + k4 * 4) = v;
        }
        __syncthreads();

        // ---- per-row stats (sum, sumsq) from the staged tile ----
        #pragma unroll
        for (int p = 0; p < 8; p++) {
            int row = wrp * 32 + p * 4 + rloc;
            const float* xr = xs + row * KP + sub * 8;
            float4 a = *(const float4*)(xr);
            float4 b = *(const float4*)(xr + 4);
            float s = ((a.x + a.y) + (a.z + a.w)) + ((b.x + b.y) + (b.z + b.w));
            float q = a.x * a.x;
            q = fmaf(a.y, a.y, q); q = fmaf(a.z, a.z, q); q = fmaf(a.w, a.w, q);
            q = fmaf(b.x, b.x, q); q = fmaf(b.y, b.y, q);
            q = fmaf(b.z, b.z, q); q = fmaf(b.w, b.w, q);
            #pragma unroll
            for (int m = 1; m < 8; m <<= 1) {
                s += __shfl_xor_sync(0xffffffffu, s, m);
                q += __shfl_xor_sync(0xffffffffu, q, m);
            }
            if (sub == 0) { sumS[row] += s; sqS[row] += q; }
        }

        // ---- main FMA loop ----
        const float* xbase = xs + rg * 8 * KP;
        const float* wbase = ws + cg * 4 * KP;
        #pragma unroll 4
        for (int k4 = 0; k4 < KC / 4; k4++) {
            float4 wv[4];
            #pragma unroll
            for (int j = 0; j < 4; j++)
                wv[j] = *(const float4*)(wbase + j * KP + k4 * 4);
            #pragma unroll
            for (int i = 0; i < 8; i++) {
                float4 xv = *(const float4*)(xbase + i * KP + k4 * 4);
                #pragma unroll
                for (int j = 0; j < 4; j++) {
                    acc[i][j] = fmaf(xv.x, wv[j].x, acc[i][j]);
                    acc[i][j] = fmaf(xv.y, wv[j].y, acc[i][j]);
                    acc[i][j] = fmaf(xv.z, wv[j].z, acc[i][j]);
                    acc[i][j] = fmaf(xv.w, wv[j].w, acc[i][j]);
                }
            }
        }
        __syncthreads();
    }

    // ---- stage dots to smem (reuse xs), stride 33 ----
    float* dotS = xs;
    #pragma unroll
    for (int i = 0; i < 8; i++)
        #pragma unroll
        for (int j = 0; j < 4; j++)
            dotS[(rg * 8 + i) * 33 + (cg * 4 + j)] = acc[i][j];
    __syncthreads();

    // ---- epilogue: per-row normalization correction + L1/L2/L3 ----
    const int j = lane;                 // output index 0..31
    const float invD  = 1.0f / (float)D_IN;
    const float invDm = 1.0f / (float)(D_IN - 1);
    for (int p = 0; p < 32; p++) {
        int row = wrp * 32 + p;
        float mean = sumS[row] * invD;
        float var  = (sqS[row] - (float)D_IN * mean * mean) * invDm;
        float rstd = rsqrtf(var);
        float d    = dotS[row * 33 + j];
        float y    = fmaf(d - mean * ScS[j], rstd, b1S[j]);
        y = fmaxf(y, 0.01f * y);                       // LeakyReLU
        float a2 = b2S[j];
        #pragma unroll
        for (int i = 0; i < H1; i++) {
            float hi = __shfl_sync(0xffffffffu, y, i);
            a2 = fmaf(w2S[j * 33 + i], hi, a2);
        }
        a2 = fmaxf(a2, 0.01f * a2);
        float a3 = b3S[j];
        #pragma unroll
        for (int i = 0; i < H1; i++) {
            float hi = __shfl_sync(0xffffffffu, a2, i);
            a3 = fmaf(w3S[j * 33 + i], hi, a3);
        }
        a3 = fmaxf(a3, 0.01f * a3);
        if (j < OUT_N)
            out[(size_t)(rowbase + row) * OUT_N + j] = a3;
    }
}

// ---------------------------------------------------------------------------
extern "C" void kernel_launch(void* const* d_in, const int* in_sizes, int n_in,
                              void* d_out, int out_size) {
    const float* x  = (const float*)d_in[0];
    const float* w1 = (const float*)d_in[1];
    const float* b1 = (const float*)d_in[2];
    const float* w2 = (const float*)d_in[3];
    const float* b2 = (const float*)d_in[4];
    const float* w3 = (const float*)d_in[5];
    const float* b3 = (const float*)d_in[6];
    float* out = (float*)d_out;

    static bool attr_set = false;
    const int smem_bytes = (R_TILE * KP + H1 * KP + 2 * R_TILE + 2 * H1 * 33 + 4 * H1) * 4;
    if (!attr_set) {
        cudaFuncSetAttribute(fused_kernel,
                             cudaFuncAttributeMaxDynamicSharedMemorySize, smem_bytes);
        attr_set = true;
    }

    colsum_kernel<<<1, 1024>>>(w1);
    fused_kernel<<<N_ROWS / R_TILE, NTHREADS, smem_bytes>>>(x, w1, b1, w2, b2, w3, b3, out);
}